// round 1
// baseline (speedup 1.0000x reference)
#include <cuda_runtime.h>
#include <math.h>

// BinEmbedding: out[p] = emb_table[tok(x[p])], tok = 0 for NaN, else
// clamp(count(bins <= x) - 1, 0) + 1.
//
// Shapes: x (16*65536,) f32, bins (256,) f32, emb_table (257*64,) f32,
// out (16*65536*64,) f32.
//
// Strategy: HBM-write-bound (268 MB out). 16 lanes per position, each lane
// stores one float4 -> fully coalesced 256B row writes. Binary search over
// bins held in shared memory (broadcast reads). emb_table gather via __ldg
// (64 KB, L1-resident).

#define NUM_BINS 256
#define H 64
#define LANES_PER_POS 16          // H floats / 4 per float4
#define POS_PER_BLOCK 16          // 256 threads / 16 lanes

__global__ __launch_bounds__(256) void bin_embed_kernel(
    const float* __restrict__ x,
    const float* __restrict__ bins,
    const float* __restrict__ emb,     // (NUM_BINS+1) * H floats
    float4* __restrict__ out,          // n_pos * 16 float4
    int n_pos)
{
    __shared__ float sbins[NUM_BINS];
    int tid = threadIdx.x;
    if (tid < NUM_BINS) sbins[tid] = bins[tid];
    __syncthreads();

    int group = tid >> 4;      // which position within block [0,16)
    int sub   = tid & 15;      // which float4 within the row [0,16)
    int pos   = blockIdx.x * POS_PER_BLOCK + group;
    if (pos >= n_pos) return;

    float v = __ldg(&x[pos]);

    int tok;
    if (isnan(v)) {
        tok = 0;
    } else {
        // count = number of bins <= v  (searchsorted side='right')
        // branch-free binary search, NUM_BINS is exactly 256
        int count = 0;
        #pragma unroll
        for (int s = NUM_BINS >> 1; s > 0; s >>= 1) {
            if (sbins[count + s - 1] <= v) count += s;
        }
        int idx = count - 1;
        if (idx < 0) idx = 0;
        tok = idx + 1;
    }

    const float4* row = reinterpret_cast<const float4*>(emb + tok * H);
    out[(size_t)pos * LANES_PER_POS + sub] = __ldg(&row[sub]);
}

extern "C" void kernel_launch(void* const* d_in, const int* in_sizes, int n_in,
                              void* d_out, int out_size)
{
    const float* x    = (const float*)d_in[0];
    const float* bins = (const float*)d_in[1];
    const float* emb  = (const float*)d_in[2];
    float4* out = (float4*)d_out;

    int n_pos = in_sizes[0];                      // B * L = 1,048,576
    int blocks = (n_pos + POS_PER_BLOCK - 1) / POS_PER_BLOCK;

    bin_embed_kernel<<<blocks, 256>>>(x, bins, emb, out, n_pos);
}

// round 2
// speedup vs baseline: 1.7512x; 1.7512x over previous
#include <cuda_runtime.h>
#include <math.h>

// BinEmbedding: out[p] = emb_table[tok(x[p])]
//   tok = 0 if isnan(x), else clamp(count(bins <= x) - 1, 0) + 1
//
// Shapes: x (16*65536,) f32, bins (256,) f32, emb_table (257*64,) f32,
// out (16*65536*64,) f32 = 268 MB written.
//
// R2 design: decoupled search/copy.
//   Phase 1: 1 thread per position does the binary search (no 16x redundancy).
//            Tokens parked in smem.
//   Phase 2: unrolled gather+store loop, independent iterations for MLP.
// Streaming stores (__stcs) keep L2 for the 64 KB table.

#define NUM_BINS 256
#define H 64
#define F4_PER_ROW 16              // H/4
#define THREADS 256
#define PPB 512                    // positions per block (2 per thread in search)

__global__ __launch_bounds__(THREADS) void bin_embed_kernel(
    const float*  __restrict__ x,
    const float*  __restrict__ bins,
    const float4* __restrict__ emb4,   // (NUM_BINS+1) * 16 float4
    float4*       __restrict__ out,    // n_pos * 16 float4
    int n_pos)
{
    __shared__ float sbins[NUM_BINS];
    __shared__ int   stok[PPB];

    const int tid  = threadIdx.x;
    const int base = blockIdx.x * PPB;

    sbins[tid] = bins[tid];            // THREADS == NUM_BINS == 256
    __syncthreads();

    // ---- Phase 1: token search, one thread per position ----
    #pragma unroll
    for (int j = 0; j < PPB / THREADS; j++) {
        int p = base + tid + j * THREADS;
        int tok = 0;
        if (p < n_pos) {
            float v = __ldg(&x[p]);
            if (!isnan(v)) {
                // count = #(bins <= v)  (searchsorted side='right'), NUM_BINS=256
                int c = 0;
                #pragma unroll
                for (int s = NUM_BINS >> 1; s > 0; s >>= 1) {
                    if (sbins[c + s - 1] <= v) c += s;
                }
                int idx = c - 1;
                tok = (idx < 0 ? 0 : idx) + 1;
            }
        }
        stok[tid + j * THREADS] = tok;
    }
    __syncthreads();

    // ---- Phase 2: gather + coalesced streaming stores ----
    // Block tile = PPB*16 float4s; each thread does 32 independent iterations.
    const size_t outbase = (size_t)base * F4_PER_ROW;
    const int    iters   = PPB * F4_PER_ROW / THREADS;   // 32

    #pragma unroll 4
    for (int i = 0; i < iters; i++) {
        int idx = tid + i * THREADS;          // float4 index inside block tile
        int p   = base + (idx >> 4);
        if (p >= n_pos) break;
        int tok = stok[idx >> 4];
        int sub = idx & 15;
        float4 val = __ldg(&emb4[tok * F4_PER_ROW + sub]);
        __stcs(&out[outbase + idx], val);
    }
}

extern "C" void kernel_launch(void* const* d_in, const int* in_sizes, int n_in,
                              void* d_out, int out_size)
{
    const float*  x    = (const float*)d_in[0];
    const float*  bins = (const float*)d_in[1];
    const float4* emb4 = (const float4*)d_in[2];
    float4* out = (float4*)d_out;

    int n_pos  = in_sizes[0];                          // B*L = 1,048,576
    int blocks = (n_pos + PPB - 1) / PPB;              // 2048

    bin_embed_kernel<<<blocks, THREADS>>>(x, bins, emb4, out, n_pos);
}